// round 14
// baseline (speedup 1.0000x reference)
#include <cuda_runtime.h>
#include <cuda_fp16.h>
#include <cstdint>

#define BB 2
#define TT 2048
#define DD 1024
#define HH 16
#define DH 64
#define MM (BB*TT)   // 4096

// ---------------- scratch (device globals, no runtime alloc) ----------------
__device__ __align__(16) __half g_Af[3][MM*DD];   // GEMM A fp16 per z (slot 0 reused for attn out)
__device__ __align__(16) __half g_Wf[4][DD*DD];   // W^T fp16 [slot][N][K]
__device__ __align__(16) __half g_Qh[MM*DD];      // Q proj fp16 (pre-scaled 1/32)
__device__ __align__(16) __half g_Kh[MM*DD];      // K proj fp16 (COMPACTED rows)
__device__ __align__(16) __half g_Vf[MM*DD];      // V proj fp16 (COMPACTED rows)
__device__ int g_idx[BB*TT];                      // compacted key -> orig t
__device__ __align__(16) int g_vmask[BB*TT];      // 1 if compacted pos valid
__device__ int g_ntiles[BB];                      // ceil(count/64)

// ---------------- PTX helpers (arch-generic sm_80+) ----------
__device__ __forceinline__ uint32_t smem_u32(const void* p) {
    uint32_t a;
    asm("{ .reg .u64 t; cvta.to.shared.u64 t, %1; cvt.u32.u64 %0, t; }" : "=r"(a) : "l"(p));
    return a;
}
__device__ __forceinline__ void cp16(uint32_t s, const void* g) {
    asm volatile("cp.async.cg.shared.global [%0], [%1], 16;" :: "r"(s), "l"(g));
}
#define CP_COMMIT() asm volatile("cp.async.commit_group;" ::: "memory")
#define CP_WAIT1()  asm volatile("cp.async.wait_group 1;" ::: "memory")
#define CP_WAIT0()  asm volatile("cp.async.wait_group 0;" ::: "memory")

__device__ __forceinline__ void ldsm4(uint32_t& r0, uint32_t& r1, uint32_t& r2,
                                      uint32_t& r3, uint32_t a) {
    asm volatile("ldmatrix.sync.aligned.m8n8.x4.shared.b16 {%0,%1,%2,%3}, [%4];"
                 : "=r"(r0), "=r"(r1), "=r"(r2), "=r"(r3) : "r"(a));
}
__device__ __forceinline__ void ldsm4t(uint32_t& r0, uint32_t& r1, uint32_t& r2,
                                       uint32_t& r3, uint32_t a) {
    asm volatile("ldmatrix.sync.aligned.m8n8.x4.trans.shared.b16 {%0,%1,%2,%3}, [%4];"
                 : "=r"(r0), "=r"(r1), "=r"(r2), "=r"(r3) : "r"(a));
}
__device__ __forceinline__ void ldsm2(uint32_t& r0, uint32_t& r1, uint32_t a) {
    asm volatile("ldmatrix.sync.aligned.m8n8.x2.shared.b16 {%0,%1}, [%2];"
                 : "=r"(r0), "=r"(r1) : "r"(a));
}
__device__ __forceinline__ void mma_fp(float* c, const uint32_t* a, const uint32_t* b) {
    asm volatile(
        "mma.sync.aligned.m16n8k16.row.col.f32.f16.f16.f32 "
        "{%0,%1,%2,%3}, {%4,%5,%6,%7}, {%8,%9}, {%0,%1,%2,%3};"
        : "+f"(c[0]), "+f"(c[1]), "+f"(c[2]), "+f"(c[3])
        : "r"(a[0]), "r"(a[1]), "r"(a[2]), "r"(a[3]), "r"(b[0]), "r"(b[1]));
}
__device__ __forceinline__ uint32_t pack_h2(float a, float b) {
    __half2 h = __floats2half2_rn(a, b);
    return *reinterpret_cast<uint32_t*>(&h);
}

// ---------------------------------------------------------------------------
// build_idx: deterministic per-batch compaction of valid keys.
// grid = BB, block = 512.
// ---------------------------------------------------------------------------
__global__ __launch_bounds__(512) void build_idx(const int* __restrict__ mask)
{
    __shared__ int wsum[16];
    __shared__ int s_cnt;
    const int b = blockIdx.x, tid = threadIdx.x;
    const int lane = tid & 31, wid = tid >> 5;

    int m[4];
    const int base = b * TT + tid * 4;
    #pragma unroll
    for (int i = 0; i < 4; i++) m[i] = (mask[base + i] != 0) ? 1 : 0;
    const int tot = m[0] + m[1] + m[2] + m[3];

    int scan = tot;
    #pragma unroll
    for (int ofs = 1; ofs < 32; ofs <<= 1) {
        int v = __shfl_up_sync(0xffffffffu, scan, ofs);
        if (lane >= ofs) scan += v;
    }
    if (lane == 31) wsum[wid] = scan;
    __syncthreads();
    if (wid == 0) {
        int v = (lane < 16) ? wsum[lane] : 0;
        #pragma unroll
        for (int ofs = 1; ofs < 16; ofs <<= 1) {
            int t = __shfl_up_sync(0xffffffffu, v, ofs);
            if (lane >= ofs) v += t;
        }
        if (lane < 16) wsum[lane] = v;
        if (lane == 15) s_cnt = v;
    }
    __syncthreads();

    int off = ((wid == 0) ? 0 : wsum[wid - 1]) + scan - tot;
    #pragma unroll
    for (int i = 0; i < 4; i++)
        if (m[i]) g_idx[b * TT + off++] = tid * 4 + i;

    const int cnt = s_cnt;
    #pragma unroll
    for (int i = 0; i < 4; i++) {
        const int j = tid * 4 + i;
        g_vmask[b * TT + j] = (j < cnt) ? 1 : 0;
        if (j >= cnt) g_idx[b * TT + j] = 0;   // padded tail -> row 0
    }
    if (tid == 0) g_ntiles[b] = (cnt + 63) >> 6;
}

// ---------------------------------------------------------------------------
// convertA3: fp32 -> fp16 GEMM A operands.
// z=0: q straight copy.  z=1/2: k/v rows GATHERED through g_idx (compacted).
// grid (MM*DD/1024, 1, 3)
// ---------------------------------------------------------------------------
__global__ __launch_bounds__(256) void convertA3(
    const float* __restrict__ q, const float* __restrict__ k,
    const float* __restrict__ v)
{
    const int z = blockIdx.z;
    const int i = (blockIdx.x * 256 + threadIdx.x) * 4;

    const float* src;
    if (z == 0) {
        src = q + i;
    } else {
        const int row = i >> 10;
        const int b   = row >> 11;
        const int j   = row & 2047;
        const int col = i & 1023;
        const int torig = g_idx[b * TT + j];
        const float* base = (z == 1) ? k : v;
        src = base + ((size_t)(b * TT + torig) << 10) + col;
    }
    float4 x = *reinterpret_cast<const float4*>(src);
    uint2 o;
    o.x = pack_h2(x.x, x.y);
    o.y = pack_h2(x.z, x.w);
    *reinterpret_cast<uint2*>(&g_Af[z][i]) = o;
}

// ---------------------------------------------------------------------------
// convertW4: fp32 W[K,N] -> fp16 W^T [N,K], slots 0..3.
// grid (DD/32, DD/32, 4), block (32, 8)
// ---------------------------------------------------------------------------
__global__ __launch_bounds__(256) void convertW4(
    const float* __restrict__ Wq, const float* __restrict__ Wk,
    const float* __restrict__ Wv, const float* __restrict__ Wo)
{
    __shared__ float tile[32][33];
    const int z = blockIdx.z;
    const float* W = (z == 0) ? Wq : (z == 1) ? Wk : (z == 2) ? Wv : Wo;
    const int n0 = blockIdx.x * 32;
    const int k0 = blockIdx.y * 32;
    const int tx = threadIdx.x, ty = threadIdx.y;

    #pragma unroll
    for (int r = 0; r < 4; r++)
        tile[ty + r * 8][tx] = W[(size_t)(k0 + ty + r * 8) * DD + n0 + tx];
    __syncthreads();

    #pragma unroll
    for (int r = 0; r < 4; r++) {
        const int n = ty + r * 8;
        g_Wf[z][(size_t)(n0 + n) * DD + k0 + tx] = __float2half_rn(tile[tx][n]);
    }
}

// ---------------------------------------------------------------------------
// fp16 HMMA GEMM: C[M,N] = A[M,K] @ W^T[N,K] + bias
// 128x128 CTA tile, 4 warps of 64x64 (125 B smem per MMA vs 192 at 64x32),
// BK=64, 3-stage cp.async pipeline, 128 threads.
// final=0: grid (8,32,3) z->q/k/v; padded-tail K/V CTAs exit early.
// final=1: grid (8,32,1) A slot 0, W slot 3, fp32 out.
// ---------------------------------------------------------------------------
#define GPITCH   144
#define TILE_B   (128 * GPITCH)      // 18432
#define BUF_B    (2 * TILE_B)        // 36864 (A + B)
#define GSM_TOT  (3 * BUF_B)         // 110592, 3 stages

__global__ __launch_bounds__(128, 2) void mma_gemm(
    const float* __restrict__ b0, const float* __restrict__ b1,
    const float* __restrict__ b2, float* __restrict__ Cp, int final_)
{
    extern __shared__ char smem[];
    const uint32_t sb = smem_u32(smem);
    const int tid  = threadIdx.x;
    const int wid  = tid >> 5;          // 0..3
    const int lane = tid & 31;
    const int warp_m = wid & 1;         // 64-row half
    const int warp_n = wid >> 1;        // 64-col half

    const int z    = final_ ? 0 : blockIdx.z;
    const int ws   = final_ ? 3 : z;
    const int mode = final_ ? 3 : z;    // 0->Qh(/32), 1->Kh, 2->Vf, 3->Cp fp32
    const float* bias = (final_ || z == 0) ? b0 : (z == 1 ? b1 : b2);

    const int aBase = blockIdx.y * 128;

    if (!final_ && z >= 1) {
        const int bb = aBase >> 11;
        if ((aBase & 2047) >= g_ntiles[bb] * 64) return;
    }

    const int bBase = blockIdx.x * 128;
    const __half* srcA = g_Af[z] + (size_t)aBase * DD;
    const __half* srcW = g_Wf[ws] + (size_t)bBase * DD;

    float acc[4][8][4];
    #pragma unroll
    for (int i = 0; i < 4; i++)
        #pragma unroll
        for (int j = 0; j < 8; j++)
            #pragma unroll
            for (int r = 0; r < 4; r++) acc[i][j][r] = 0.f;

    auto load_chunk = [&](int c, int buf) {
        const int c0 = c * 64;
        const uint32_t base = sb + buf * BUF_B;
        #pragma unroll
        for (int it = 0; it < 16; it++) {
            const int idx = tid + it * 128;        // 0..2047
            const int t2  = idx >> 10;             // 0: A, 1: W
            const int rem = idx & 1023;
            const int row = rem >> 3;
            const int seg = rem & 7;
            const __half* s = (t2 == 0) ? srcA : srcW;
            cp16(base + t2 * TILE_B + row * GPITCH + seg * 16,
                 s + (size_t)row * DD + c0 + seg * 8);
        }
    };

    load_chunk(0, 0); CP_COMMIT();
    load_chunk(1, 1); CP_COMMIT();

    int cb = 0, lb = 2;
    for (int c = 0; c < 16; c++) {
        if (c < 15) { CP_WAIT1(); } else { CP_WAIT0(); }
        __syncthreads();

        if (c + 2 < 16) {
            load_chunk(c + 2, lb);
            CP_COMMIT();
        }

        const uint32_t sA = sb + cb * BUF_B;
        const uint32_t sB = sA + TILE_B;

        #pragma unroll
        for (int ks = 0; ks < 4; ks++) {
            const int kb = ks * 32;
            uint32_t af[4][4], bf[8][2];

            const int arow = (lane & 15);
            const uint32_t acol = ((lane >> 4) << 4) + kb;
            #pragma unroll
            for (int mt = 0; mt < 4; mt++) {
                const uint32_t ro = (uint32_t)(warp_m * 64 + mt * 16 + arow) * GPITCH + acol;
                ldsm4(af[mt][0], af[mt][1], af[mt][2], af[mt][3], sA + ro);
            }
            const int brow = (lane & 7);
            const uint32_t bcol = (((lane >> 3) & 1) << 4) + kb;
            #pragma unroll
            for (int nt = 0; nt < 8; nt++) {
                const uint32_t ro = (uint32_t)(warp_n * 64 + nt * 8 + brow) * GPITCH + bcol;
                ldsm2(bf[nt][0], bf[nt][1], sB + ro);
            }

            #pragma unroll
            for (int mt = 0; mt < 4; mt++)
                #pragma unroll
                for (int nt = 0; nt < 8; nt++)
                    mma_fp(acc[mt][nt], af[mt], bf[nt]);
        }

        cb = (cb == 2) ? 0 : cb + 1;
        lb = (lb == 2) ? 0 : lb + 1;
    }

    // ---- epilogue ----
    const float qs = (mode == 0) ? 0.03125f : 1.0f;
    #pragma unroll
    for (int mt = 0; mt < 4; mt++) {
        const int row0 = aBase + warp_m * 64 + mt * 16 + (lane >> 2);
        #pragma unroll
        for (int nt = 0; nt < 8; nt++) {
            const int col = bBase + warp_n * 64 + nt * 8 + (lane & 3) * 2;
            const float bb0 = bias[col], bb1 = bias[col + 1];
            float2 v0 = { acc[mt][nt][0] + bb0, acc[mt][nt][1] + bb1 };
            float2 v1 = { acc[mt][nt][2] + bb0, acc[mt][nt][3] + bb1 };
            if (mode == 3) {
                *reinterpret_cast<float2*>(Cp + (size_t)row0 * DD + col) = v0;
                *reinterpret_cast<float2*>(Cp + (size_t)(row0 + 8) * DD + col) = v1;
            } else {
                __half* D = (mode == 0) ? g_Qh : (mode == 1) ? g_Kh : g_Vf;
                *reinterpret_cast<uint32_t*>(D + (size_t)row0 * DD + col) =
                    pack_h2(v0.x * qs, v0.y * qs);
                *reinterpret_cast<uint32_t*>(D + (size_t)(row0 + 8) * DD + col) =
                    pack_h2(v1.x * qs, v1.y * qs);
            }
        }
    }
}

// ---------------------------------------------------------------------------
// Tensor-core flash attention over COMPACTED keys (fp16, 3-stage pipeline).
// grid = (T/128 qtiles, B*H), block = 256 (8 warps, 16 q-rows each).
// V transposed at ldmatrix time (.trans). Output -> g_Af[0] fp16.
// ---------------------------------------------------------------------------
#define APB    144            // smem row pitch bytes (64 halves + pad)
#define OFF_K  0
#define OFF_V  9216
#define OFF_MS 18432
#define ABUF   18688
#define ASM_TOT (3*ABUF)      // 56064, 3 stages

__global__ __launch_bounds__(256, 2) void attn_mma()
{
    extern __shared__ char smema[];
    const uint32_t sb = smem_u32(smema);
    const int tid  = threadIdx.x;
    const int lane = tid & 31;
    const int w    = tid >> 5;          // 0..7
    const int bh   = blockIdx.y;
    const int b    = bh >> 4, h = bh & 15;
    const int q0   = blockIdx.x * 128;
    const int c0   = (lane & 3) * 2;
    const float NEGINF = -__int_as_float(0x7f800000);

    const int ntk = g_ntiles[b];

    // preload Q A-frags (fp16, pre-scaled 1/32)
    uint32_t qa[4][4];
    {
        const int r = q0 + w * 16 + (lane >> 2);
        const __half* Qb = g_Qh + (size_t)(b * TT + r) * DD + h * 64;
        #pragma unroll
        for (int t = 0; t < 4; t++) {
            qa[t][0] = *reinterpret_cast<const uint32_t*>(Qb + t * 16 + c0);
            qa[t][1] = *reinterpret_cast<const uint32_t*>(Qb + 8 * DD + t * 16 + c0);
            qa[t][2] = *reinterpret_cast<const uint32_t*>(Qb + t * 16 + 8 + c0);
            qa[t][3] = *reinterpret_cast<const uint32_t*>(Qb + 8 * DD + t * 16 + 8 + c0);
        }
    }

    auto load_tiles = [&](int kt, int bufsel) {
        const uint32_t base = sb + bufsel * ABUF;
        const int s0 = kt * 64;
        #pragma unroll
        for (int it = 0; it < 2; it++) {
            const int idx = tid + it * 256;       // 0..511
            const int row = idx >> 3, seg = idx & 7;
            const size_t g = (size_t)(b * TT + s0 + row) * DD + h * 64 + seg * 8;
            cp16(base + OFF_K + row * APB + seg * 16, g_Kh + g);
            cp16(base + OFF_V + row * APB + seg * 16, g_Vf + g);
        }
        if (tid < 16) cp16(base + OFF_MS + tid * 16, g_vmask + b * TT + s0 + tid * 4);
    };

    float o[8][4];
    #pragma unroll
    for (int n = 0; n < 8; n++)
        #pragma unroll
        for (int r = 0; r < 4; r++) o[n][r] = 0.f;
    float m0 = -1e30f, m1 = -1e30f, l0 = 0.f, l1 = 0.f;

    load_tiles(0, 0); CP_COMMIT();
    if (ntk > 1) { load_tiles(1, 1); CP_COMMIT(); }

    int cb = 0, lb = 2;
    for (int kt = 0; kt < ntk; kt++) {
        if (kt < ntk - 1) { CP_WAIT1(); } else { CP_WAIT0(); }
        __syncthreads();

        if (kt + 2 < ntk) {
            load_tiles(kt + 2, lb);
            CP_COMMIT();
        }

        const uint32_t base = sb + cb * ABUF;

        // ---- S = Q K^T (fp16, fp32 accum) ----
        float sf[8][4];
        #pragma unroll
        for (int j = 0; j < 8; j++) {
            sf[j][0] = sf[j][1] = sf[j][2] = sf[j][3] = 0.f;
            uint32_t kA[4], kB[4];
            const uint32_t ka = base + OFF_K + (j * 8 + (lane & 7)) * APB
                              + ((lane >> 3) & 3) * 16;
            ldsm4(kA[0], kA[1], kA[2], kA[3], ka);
            ldsm4(kB[0], kB[1], kB[2], kB[3], ka + 64);
            mma_fp(sf[j], qa[0], &kA[0]);
            mma_fp(sf[j], qa[1], &kA[2]);
            mma_fp(sf[j], qa[2], &kB[0]);
            mma_fp(sf[j], qa[3], &kB[2]);
        }

        // ---- mask (incl. padded tail) + online softmax (p in-place in sf) ----
        float mx0 = NEGINF, mx1 = NEGINF;
        #pragma unroll
        for (int j = 0; j < 8; j++) {
            const int2 mk = *reinterpret_cast<const int2*>(
                smema + cb * ABUF + OFF_MS + (j * 8 + c0) * 4);
            sf[j][0] = mk.x ? sf[j][0] : NEGINF;
            sf[j][1] = mk.y ? sf[j][1] : NEGINF;
            sf[j][2] = mk.x ? sf[j][2] : NEGINF;
            sf[j][3] = mk.y ? sf[j][3] : NEGINF;
            mx0 = fmaxf(mx0, fmaxf(sf[j][0], sf[j][1]));
            mx1 = fmaxf(mx1, fmaxf(sf[j][2], sf[j][3]));
        }
        mx0 = fmaxf(mx0, __shfl_xor_sync(0xffffffffu, mx0, 1));
        mx0 = fmaxf(mx0, __shfl_xor_sync(0xffffffffu, mx0, 2));
        mx1 = fmaxf(mx1, __shfl_xor_sync(0xffffffffu, mx1, 1));
        mx1 = fmaxf(mx1, __shfl_xor_sync(0xffffffffu, mx1, 2));

        const float mn0 = fmaxf(m0, mx0), mn1 = fmaxf(m1, mx1);
        const float sc0 = __expf(m0 - mn0), sc1 = __expf(m1 - mn1);
        float sum0 = 0.f, sum1 = 0.f;
        #pragma unroll
        for (int j = 0; j < 8; j++) {
            sf[j][0] = __expf(sf[j][0] - mn0);
            sf[j][1] = __expf(sf[j][1] - mn0);
            sf[j][2] = __expf(sf[j][2] - mn1);
            sf[j][3] = __expf(sf[j][3] - mn1);
            sum0 += sf[j][0] + sf[j][1];
            sum1 += sf[j][2] + sf[j][3];
        }
        sum0 += __shfl_xor_sync(0xffffffffu, sum0, 1);
        sum0 += __shfl_xor_sync(0xffffffffu, sum0, 2);
        sum1 += __shfl_xor_sync(0xffffffffu, sum1, 1);
        sum1 += __shfl_xor_sync(0xffffffffu, sum1, 2);
        l0 = l0 * sc0 + sum0;
        l1 = l1 * sc1 + sum1;
        m0 = mn0;
        m1 = mn1;
        #pragma unroll
        for (int n = 0; n < 8; n++) {
            o[n][0] *= sc0; o[n][1] *= sc0;
            o[n][2] *= sc1; o[n][3] *= sc1;
        }

        // ---- pack P -> fp16 A-frags ----
        uint32_t pa[4][4];
        #pragma unroll
        for (int t = 0; t < 4; t++) {
            pa[t][0] = pack_h2(sf[2*t][0],   sf[2*t][1]);
            pa[t][1] = pack_h2(sf[2*t][2],   sf[2*t][3]);
            pa[t][2] = pack_h2(sf[2*t+1][0], sf[2*t+1][1]);
            pa[t][3] = pack_h2(sf[2*t+1][2], sf[2*t+1][3]);
        }

        // ---- O += P V  (V row-major in smem, transposed by ldsm.trans) ----
        #pragma unroll
        for (int n = 0; n < 8; n++) {
            uint32_t vA[4], vB[4];
            const uint32_t va = base + OFF_V + (uint32_t)lane * APB + n * 16;
            ldsm4t(vA[0], vA[1], vA[2], vA[3], va);              // keys 0..31
            ldsm4t(vB[0], vB[1], vB[2], vB[3], va + 32 * APB);   // keys 32..63
            mma_fp(o[n], pa[0], &vA[0]);
            mma_fp(o[n], pa[1], &vA[2]);
            mma_fp(o[n], pa[2], &vB[0]);
            mma_fp(o[n], pa[3], &vB[2]);
        }

        cb = (cb == 2) ? 0 : cb + 1;
        lb = (lb == 2) ? 0 : lb + 1;
    }

    // ---- epilogue: o/l -> fp16 directly into final-GEMM A slot 0 ----
    const float i0 = 1.f / l0, i1 = 1.f / l1;
    const int r0 = q0 + w * 16 + (lane >> 2);
    #pragma unroll
    for (int n = 0; n < 8; n++) {
        const size_t a0 = (size_t)(b * TT + r0) * DD + h * 64 + n * 8 + c0;
        const size_t a1 = a0 + 8 * DD;
        *reinterpret_cast<uint32_t*>(&g_Af[0][a0]) = pack_h2(o[n][0] * i0, o[n][1] * i0);
        *reinterpret_cast<uint32_t*>(&g_Af[0][a1]) = pack_h2(o[n][2] * i1, o[n][3] * i1);
    }
}

// ---------------------------------------------------------------------------
// Launch
// ---------------------------------------------------------------------------
extern "C" void kernel_launch(void* const* d_in, const int* in_sizes, int n_in,
                              void* d_out, int out_size)
{
    const float* q    = (const float*)d_in[0];
    const float* k    = (const float*)d_in[1];
    const float* v    = (const float*)d_in[2];
    const int*   mask = (const int*)  d_in[3];
    const float* Wq   = (const float*)d_in[4];
    const float* bq   = (const float*)d_in[5];
    const float* Wk   = (const float*)d_in[6];
    const float* bk   = (const float*)d_in[7];
    const float* Wv   = (const float*)d_in[8];
    const float* bv   = (const float*)d_in[9];
    const float* Wo   = (const float*)d_in[10];
    const float* bo   = (const float*)d_in[11];
    float* out = (float*)d_out;

    cudaFuncSetAttribute(mma_gemm, cudaFuncAttributeMaxDynamicSharedMemorySize, GSM_TOT);
    cudaFuncSetAttribute(attn_mma, cudaFuncAttributeMaxDynamicSharedMemorySize, ASM_TOT);

    const dim3 cgrid(MM * DD / 4 / 256, 1, 3);
    const dim3 wgrid(DD / 32, DD / 32, 4);
    const dim3 wblk(32, 8);
    const dim3 pgrid(DD / 128, MM / 128, 3);   // batched projections
    const dim3 fgrid(DD / 128, MM / 128, 1);   // final GEMM
    const dim3 agrid(TT / 128, BB * HH);

    build_idx<<<BB, 512>>>(mask);                              // compaction FIRST
    convertW4<<<wgrid, wblk>>>(Wq, Wk, Wv, Wo);                // W^T fp16
    convertA3<<<cgrid, 256>>>(q, k, v);                        // A fp16 (k/v gathered)

    mma_gemm<<<pgrid, 128, GSM_TOT>>>(bq, bk, bv, nullptr, 0); // Qh + compacted Kh/Vf

    attn_mma<<<agrid, 256, ASM_TOT>>>();                       // -> g_Af[0]

    mma_gemm<<<fgrid, 128, GSM_TOT>>>(bo, bo, bo, out, 1);     // -> out
}

// round 15
// speedup vs baseline: 1.0096x; 1.0096x over previous
#include <cuda_runtime.h>
#include <cuda_fp16.h>
#include <cstdint>

#define BB 2
#define TT 2048
#define DD 1024
#define HH 16
#define DH 64
#define MM (BB*TT)   // 4096

// ---------------- scratch (device globals, no runtime alloc) ----------------
__device__ __align__(16) __half g_Af[3][MM*DD];   // GEMM A fp16 per z (slot 0 reused for attn out)
__device__ __align__(16) __half g_Wf[4][DD*DD];   // W^T fp16 [slot][N][K]
__device__ __align__(16) __half g_Qh[MM*DD];      // Q proj fp16 (pre-scaled 1/32)
__device__ __align__(16) __half g_Kh[MM*DD];      // K proj fp16 (COMPACTED rows)
__device__ __align__(16) __half g_Vf[MM*DD];      // V proj fp16 (COMPACTED rows)
__device__ int g_idx[BB*TT];                      // compacted key -> orig t
__device__ __align__(16) int g_vmask[BB*TT];      // 1 if compacted pos valid
__device__ int g_ntiles[BB];                      // ceil(count/64)

// ---------------- PTX helpers (arch-generic sm_80+) ----------
__device__ __forceinline__ uint32_t smem_u32(const void* p) {
    uint32_t a;
    asm("{ .reg .u64 t; cvta.to.shared.u64 t, %1; cvt.u32.u64 %0, t; }" : "=r"(a) : "l"(p));
    return a;
}
__device__ __forceinline__ void cp16(uint32_t s, const void* g) {
    asm volatile("cp.async.cg.shared.global [%0], [%1], 16;" :: "r"(s), "l"(g));
}
#define CP_COMMIT() asm volatile("cp.async.commit_group;" ::: "memory")
#define CP_WAIT2()  asm volatile("cp.async.wait_group 2;" ::: "memory")
#define CP_WAIT1()  asm volatile("cp.async.wait_group 1;" ::: "memory")
#define CP_WAIT0()  asm volatile("cp.async.wait_group 0;" ::: "memory")

__device__ __forceinline__ void ldsm4(uint32_t& r0, uint32_t& r1, uint32_t& r2,
                                      uint32_t& r3, uint32_t a) {
    asm volatile("ldmatrix.sync.aligned.m8n8.x4.shared.b16 {%0,%1,%2,%3}, [%4];"
                 : "=r"(r0), "=r"(r1), "=r"(r2), "=r"(r3) : "r"(a));
}
__device__ __forceinline__ void ldsm4t(uint32_t& r0, uint32_t& r1, uint32_t& r2,
                                       uint32_t& r3, uint32_t a) {
    asm volatile("ldmatrix.sync.aligned.m8n8.x4.trans.shared.b16 {%0,%1,%2,%3}, [%4];"
                 : "=r"(r0), "=r"(r1), "=r"(r2), "=r"(r3) : "r"(a));
}
__device__ __forceinline__ void ldsm2(uint32_t& r0, uint32_t& r1, uint32_t a) {
    asm volatile("ldmatrix.sync.aligned.m8n8.x2.shared.b16 {%0,%1}, [%2];"
                 : "=r"(r0), "=r"(r1) : "r"(a));
}
__device__ __forceinline__ void mma_fp(float* c, const uint32_t* a, const uint32_t* b) {
    asm volatile(
        "mma.sync.aligned.m16n8k16.row.col.f32.f16.f16.f32 "
        "{%0,%1,%2,%3}, {%4,%5,%6,%7}, {%8,%9}, {%0,%1,%2,%3};"
        : "+f"(c[0]), "+f"(c[1]), "+f"(c[2]), "+f"(c[3])
        : "r"(a[0]), "r"(a[1]), "r"(a[2]), "r"(a[3]), "r"(b[0]), "r"(b[1]));
}
__device__ __forceinline__ uint32_t pack_h2(float a, float b) {
    __half2 h = __floats2half2_rn(a, b);
    return *reinterpret_cast<uint32_t*>(&h);
}

// ---------------------------------------------------------------------------
// build_idx: deterministic per-batch compaction of valid keys.
// grid = BB, block = 512.
// ---------------------------------------------------------------------------
__global__ __launch_bounds__(512) void build_idx(const int* __restrict__ mask)
{
    __shared__ int wsum[16];
    __shared__ int s_cnt;
    const int b = blockIdx.x, tid = threadIdx.x;
    const int lane = tid & 31, wid = tid >> 5;

    int m[4];
    const int base = b * TT + tid * 4;
    #pragma unroll
    for (int i = 0; i < 4; i++) m[i] = (mask[base + i] != 0) ? 1 : 0;
    const int tot = m[0] + m[1] + m[2] + m[3];

    int scan = tot;
    #pragma unroll
    for (int ofs = 1; ofs < 32; ofs <<= 1) {
        int v = __shfl_up_sync(0xffffffffu, scan, ofs);
        if (lane >= ofs) scan += v;
    }
    if (lane == 31) wsum[wid] = scan;
    __syncthreads();
    if (wid == 0) {
        int v = (lane < 16) ? wsum[lane] : 0;
        #pragma unroll
        for (int ofs = 1; ofs < 16; ofs <<= 1) {
            int t = __shfl_up_sync(0xffffffffu, v, ofs);
            if (lane >= ofs) v += t;
        }
        if (lane < 16) wsum[lane] = v;
        if (lane == 15) s_cnt = v;
    }
    __syncthreads();

    int off = ((wid == 0) ? 0 : wsum[wid - 1]) + scan - tot;
    #pragma unroll
    for (int i = 0; i < 4; i++)
        if (m[i]) g_idx[b * TT + off++] = tid * 4 + i;

    const int cnt = s_cnt;
    #pragma unroll
    for (int i = 0; i < 4; i++) {
        const int j = tid * 4 + i;
        g_vmask[b * TT + j] = (j < cnt) ? 1 : 0;
        if (j >= cnt) g_idx[b * TT + j] = 0;   // padded tail -> row 0
    }
    if (tid == 0) g_ntiles[b] = (cnt + 63) >> 6;
}

// ---------------------------------------------------------------------------
// convert_all: one launch for A conversions AND W transposes.
// flat grid: blocks [0, 12288)  -> A slices (z = blk/4096; q copy, k/v gather)
//            blocks [12288, 16384) -> W^T slots (slot = (blk-12288)/1024)
// block = 256 threads.
// ---------------------------------------------------------------------------
__global__ __launch_bounds__(256) void convert_all(
    const float* __restrict__ q, const float* __restrict__ k,
    const float* __restrict__ v,
    const float* __restrict__ Wq, const float* __restrict__ Wk,
    const float* __restrict__ Wv, const float* __restrict__ Wo)
{
    const int blk = blockIdx.x;
    const int tid = threadIdx.x;

    if (blk < 12288) {
        // ---- A conversion: 4 fp32 -> 4 fp16 per thread ----
        const int z  = blk >> 12;            // 0..2
        const int bx = blk & 4095;
        const int i  = (bx * 256 + tid) * 4;

        const float* src;
        if (z == 0) {
            src = q + i;
        } else {
            const int row = i >> 10;
            const int b   = row >> 11;
            const int j   = row & 2047;
            const int col = i & 1023;
            const int torig = g_idx[b * TT + j];
            const float* base = (z == 1) ? k : v;
            src = base + ((size_t)(b * TT + torig) << 10) + col;
        }
        float4 x = *reinterpret_cast<const float4*>(src);
        uint2 o;
        o.x = pack_h2(x.x, x.y);
        o.y = pack_h2(x.z, x.w);
        *reinterpret_cast<uint2*>(&g_Af[z][i]) = o;
    } else {
        // ---- W transpose: 32x32 tile, flattened (32,8) indexing ----
        __shared__ float tile[32][33];
        const int wb   = blk - 12288;
        const int z    = wb >> 10;           // 0..3
        const int t2d  = wb & 1023;
        const int n0   = (t2d & 31) * 32;    // 32 N-tiles
        const int k0   = (t2d >> 5) * 32;    // 32 K-tiles
        const float* W = (z == 0) ? Wq : (z == 1) ? Wk : (z == 2) ? Wv : Wo;
        const int tx = tid & 31, ty = tid >> 5;

        #pragma unroll
        for (int r = 0; r < 4; r++)
            tile[ty + r * 8][tx] = W[(size_t)(k0 + ty + r * 8) * DD + n0 + tx];
        __syncthreads();

        #pragma unroll
        for (int r = 0; r < 4; r++) {
            const int n = ty + r * 8;
            g_Wf[z][(size_t)(n0 + n) * DD + k0 + tx] = __float2half_rn(tile[tx][n]);
        }
    }
}

// ---------------------------------------------------------------------------
// fp16 HMMA GEMM (R13 config): C[M,N] = A[M,K] @ W^T[N,K] + bias
// 128x128 CTA tile, 8 warps of 64x32, BK=64, 3-stage cp.async pipeline,
// 256 threads, row pitch 144B.
// final=0: grid (8,32,3) z->q/k/v; padded-tail K/V CTAs exit early.
// final=1: grid (8,32,1) A slot 0, W slot 3, fp32 out.
// ---------------------------------------------------------------------------
#define GPITCH   144
#define TILE_B   (128 * GPITCH)      // 18432
#define BUF_B    (2 * TILE_B)        // 36864 (A + B)
#define GSM_TOT  (3 * BUF_B)         // 110592, 3 stages

__global__ __launch_bounds__(256, 2) void mma_gemm(
    const float* __restrict__ b0, const float* __restrict__ b1,
    const float* __restrict__ b2, float* __restrict__ Cp, int final_)
{
    extern __shared__ char smem[];
    const uint32_t sb = smem_u32(smem);
    const int tid  = threadIdx.x;
    const int wid  = tid >> 5;
    const int lane = tid & 31;
    const int warp_m = wid & 1;
    const int warp_n = wid >> 1;

    const int z    = final_ ? 0 : blockIdx.z;
    const int ws   = final_ ? 3 : z;
    const int mode = final_ ? 3 : z;    // 0->Qh(/32), 1->Kh, 2->Vf, 3->Cp fp32
    const float* bias = (final_ || z == 0) ? b0 : (z == 1 ? b1 : b2);

    const int aBase = blockIdx.y * 128;

    if (!final_ && z >= 1) {
        const int bb = aBase >> 11;
        if ((aBase & 2047) >= g_ntiles[bb] * 64) return;
    }

    const int bBase = blockIdx.x * 128;
    const __half* srcA = g_Af[z] + (size_t)aBase * DD;
    const __half* srcW = g_Wf[ws] + (size_t)bBase * DD;

    float acc[4][4][4];
    #pragma unroll
    for (int i = 0; i < 4; i++)
        #pragma unroll
        for (int j = 0; j < 4; j++)
            #pragma unroll
            for (int r = 0; r < 4; r++) acc[i][j][r] = 0.f;

    auto load_chunk = [&](int c, int buf) {
        const int c0 = c * 64;
        const uint32_t base = sb + buf * BUF_B;
        #pragma unroll
        for (int it = 0; it < 8; it++) {
            const int idx = tid + it * 256;        // 0..2047
            const int t2  = idx >> 10;             // 0: A, 1: W
            const int rem = idx & 1023;
            const int row = rem >> 3;
            const int seg = rem & 7;
            const __half* s = (t2 == 0) ? srcA : srcW;
            cp16(base + t2 * TILE_B + row * GPITCH + seg * 16,
                 s + (size_t)row * DD + c0 + seg * 8);
        }
    };

    load_chunk(0, 0); CP_COMMIT();
    load_chunk(1, 1); CP_COMMIT();

    int cb = 0, lb = 2;
    for (int c = 0; c < 16; c++) {
        if (c < 15) { CP_WAIT1(); } else { CP_WAIT0(); }
        __syncthreads();

        if (c + 2 < 16) {
            load_chunk(c + 2, lb);
            CP_COMMIT();
        }

        const uint32_t sA = sb + cb * BUF_B;
        const uint32_t sB = sA + TILE_B;

        #pragma unroll
        for (int ks = 0; ks < 4; ks++) {
            const int kb = ks * 32;
            uint32_t af[4][4], bf[4][2];

            const int arow = (lane & 15);
            const uint32_t acol = ((lane >> 4) << 4) + kb;
            #pragma unroll
            for (int mt = 0; mt < 4; mt++) {
                const uint32_t ro = (uint32_t)(warp_m * 64 + mt * 16 + arow) * GPITCH + acol;
                ldsm4(af[mt][0], af[mt][1], af[mt][2], af[mt][3], sA + ro);
            }
            const int brow = (lane & 7);
            const uint32_t bcol = (((lane >> 3) & 1) << 4) + kb;
            #pragma unroll
            for (int nt = 0; nt < 4; nt++) {
                const uint32_t ro = (uint32_t)(warp_n * 32 + nt * 8 + brow) * GPITCH + bcol;
                ldsm2(bf[nt][0], bf[nt][1], sB + ro);
            }

            #pragma unroll
            for (int mt = 0; mt < 4; mt++)
                #pragma unroll
                for (int nt = 0; nt < 4; nt++)
                    mma_fp(acc[mt][nt], af[mt], bf[nt]);
        }

        cb = (cb == 2) ? 0 : cb + 1;
        lb = (lb == 2) ? 0 : lb + 1;
    }

    // ---- epilogue ----
    const float qs = (mode == 0) ? 0.03125f : 1.0f;
    #pragma unroll
    for (int mt = 0; mt < 4; mt++) {
        const int row0 = aBase + warp_m * 64 + mt * 16 + (lane >> 2);
        #pragma unroll
        for (int nt = 0; nt < 4; nt++) {
            const int col = bBase + warp_n * 32 + nt * 8 + (lane & 3) * 2;
            const float bb0 = bias[col], bb1 = bias[col + 1];
            float2 v0 = { acc[mt][nt][0] + bb0, acc[mt][nt][1] + bb1 };
            float2 v1 = { acc[mt][nt][2] + bb0, acc[mt][nt][3] + bb1 };
            if (mode == 3) {
                *reinterpret_cast<float2*>(Cp + (size_t)row0 * DD + col) = v0;
                *reinterpret_cast<float2*>(Cp + (size_t)(row0 + 8) * DD + col) = v1;
            } else {
                __half* D = (mode == 0) ? g_Qh : (mode == 1) ? g_Kh : g_Vf;
                *reinterpret_cast<uint32_t*>(D + (size_t)row0 * DD + col) =
                    pack_h2(v0.x * qs, v0.y * qs);
                *reinterpret_cast<uint32_t*>(D + (size_t)(row0 + 8) * DD + col) =
                    pack_h2(v1.x * qs, v1.y * qs);
            }
        }
    }
}

// ---------------------------------------------------------------------------
// Tensor-core flash attention over COMPACTED keys (fp16, 4-stage pipeline).
// grid = (T/128 qtiles, B*H), block = 256 (8 warps, 16 q-rows each).
// One cp.async commit group per loop iteration (empty at tail) keeps
// wait_group 2 accounting exact. V transposed via ldsm.trans.
// Output -> g_Af[0] fp16.
// ---------------------------------------------------------------------------
#define APB    144            // smem row pitch bytes (64 halves + pad)
#define OFF_K  0
#define OFF_V  9216
#define OFF_MS 18432
#define ABUF   18688
#define ASM_TOT (4*ABUF)      // 74752, 4 stages

__global__ __launch_bounds__(256, 2) void attn_mma()
{
    extern __shared__ char smema[];
    const uint32_t sb = smem_u32(smema);
    const int tid  = threadIdx.x;
    const int lane = tid & 31;
    const int w    = tid >> 5;          // 0..7
    const int bh   = blockIdx.y;
    const int b    = bh >> 4, h = bh & 15;
    const int q0   = blockIdx.x * 128;
    const int c0   = (lane & 3) * 2;
    const float NEGINF = -__int_as_float(0x7f800000);

    const int ntk = g_ntiles[b];

    // preload Q A-frags (fp16, pre-scaled 1/32)
    uint32_t qa[4][4];
    {
        const int r = q0 + w * 16 + (lane >> 2);
        const __half* Qb = g_Qh + (size_t)(b * TT + r) * DD + h * 64;
        #pragma unroll
        for (int t = 0; t < 4; t++) {
            qa[t][0] = *reinterpret_cast<const uint32_t*>(Qb + t * 16 + c0);
            qa[t][1] = *reinterpret_cast<const uint32_t*>(Qb + 8 * DD + t * 16 + c0);
            qa[t][2] = *reinterpret_cast<const uint32_t*>(Qb + t * 16 + 8 + c0);
            qa[t][3] = *reinterpret_cast<const uint32_t*>(Qb + 8 * DD + t * 16 + 8 + c0);
        }
    }

    auto load_tiles = [&](int kt, int bufsel) {
        const uint32_t base = sb + bufsel * ABUF;
        const int s0 = kt * 64;
        #pragma unroll
        for (int it = 0; it < 2; it++) {
            const int idx = tid + it * 256;       // 0..511
            const int row = idx >> 3, seg = idx & 7;
            const size_t g = (size_t)(b * TT + s0 + row) * DD + h * 64 + seg * 8;
            cp16(base + OFF_K + row * APB + seg * 16, g_Kh + g);
            cp16(base + OFF_V + row * APB + seg * 16, g_Vf + g);
        }
        if (tid < 16) cp16(base + OFF_MS + tid * 16, g_vmask + b * TT + s0 + tid * 4);
    };

    float o[8][4];
    #pragma unroll
    for (int n = 0; n < 8; n++)
        #pragma unroll
        for (int r = 0; r < 4; r++) o[n][r] = 0.f;
    float m0 = -1e30f, m1 = -1e30f, l0 = 0.f, l1 = 0.f;

    // prologue: 3 tiles in flight (empty commits if ntk small)
    #pragma unroll
    for (int p = 0; p < 3; p++) {
        if (p < ntk) load_tiles(p, p);
        CP_COMMIT();
    }

    int cb = 0, lb = 3;
    for (int kt = 0; kt < ntk; kt++) {
        CP_WAIT2();                       // tile kt's group complete
        __syncthreads();

        if (kt + 3 < ntk) load_tiles(kt + 3, lb);
        CP_COMMIT();                      // one group per iteration, may be empty

        const uint32_t base = sb + cb * ABUF;

        // ---- S = Q K^T (fp16, fp32 accum) ----
        float sf[8][4];
        #pragma unroll
        for (int j = 0; j < 8; j++) {
            sf[j][0] = sf[j][1] = sf[j][2] = sf[j][3] = 0.f;
            uint32_t kA[4], kB[4];
            const uint32_t ka = base + OFF_K + (j * 8 + (lane & 7)) * APB
                              + ((lane >> 3) & 3) * 16;
            ldsm4(kA[0], kA[1], kA[2], kA[3], ka);
            ldsm4(kB[0], kB[1], kB[2], kB[3], ka + 64);
            mma_fp(sf[j], qa[0], &kA[0]);
            mma_fp(sf[j], qa[1], &kA[2]);
            mma_fp(sf[j], qa[2], &kB[0]);
            mma_fp(sf[j], qa[3], &kB[2]);
        }

        // ---- mask (incl. padded tail) + online softmax (p in-place in sf) ----
        float mx0 = NEGINF, mx1 = NEGINF;
        #pragma unroll
        for (int j = 0; j < 8; j++) {
            const int2 mk = *reinterpret_cast<const int2*>(
                smema + cb * ABUF + OFF_MS + (j * 8 + c0) * 4);
            sf[j][0] = mk.x ? sf[j][0] : NEGINF;
            sf[j][1] = mk.y ? sf[j][1] : NEGINF;
            sf[j][2] = mk.x ? sf[j][2] : NEGINF;
            sf[j][3] = mk.y ? sf[j][3] : NEGINF;
            mx0 = fmaxf(mx0, fmaxf(sf[j][0], sf[j][1]));
            mx1 = fmaxf(mx1, fmaxf(sf[j][2], sf[j][3]));
        }
        mx0 = fmaxf(mx0, __shfl_xor_sync(0xffffffffu, mx0, 1));
        mx0 = fmaxf(mx0, __shfl_xor_sync(0xffffffffu, mx0, 2));
        mx1 = fmaxf(mx1, __shfl_xor_sync(0xffffffffu, mx1, 1));
        mx1 = fmaxf(mx1, __shfl_xor_sync(0xffffffffu, mx1, 2));

        const float mn0 = fmaxf(m0, mx0), mn1 = fmaxf(m1, mx1);
        const float sc0 = __expf(m0 - mn0), sc1 = __expf(m1 - mn1);
        float sum0 = 0.f, sum1 = 0.f;
        #pragma unroll
        for (int j = 0; j < 8; j++) {
            sf[j][0] = __expf(sf[j][0] - mn0);
            sf[j][1] = __expf(sf[j][1] - mn0);
            sf[j][2] = __expf(sf[j][2] - mn1);
            sf[j][3] = __expf(sf[j][3] - mn1);
            sum0 += sf[j][0] + sf[j][1];
            sum1 += sf[j][2] + sf[j][3];
        }
        sum0 += __shfl_xor_sync(0xffffffffu, sum0, 1);
        sum0 += __shfl_xor_sync(0xffffffffu, sum0, 2);
        sum1 += __shfl_xor_sync(0xffffffffu, sum1, 1);
        sum1 += __shfl_xor_sync(0xffffffffu, sum1, 2);
        l0 = l0 * sc0 + sum0;
        l1 = l1 * sc1 + sum1;
        m0 = mn0;
        m1 = mn1;
        #pragma unroll
        for (int n = 0; n < 8; n++) {
            o[n][0] *= sc0; o[n][1] *= sc0;
            o[n][2] *= sc1; o[n][3] *= sc1;
        }

        // ---- pack P -> fp16 A-frags ----
        uint32_t pa[4][4];
        #pragma unroll
        for (int t = 0; t < 4; t++) {
            pa[t][0] = pack_h2(sf[2*t][0],   sf[2*t][1]);
            pa[t][1] = pack_h2(sf[2*t][2],   sf[2*t][3]);
            pa[t][2] = pack_h2(sf[2*t+1][0], sf[2*t+1][1]);
            pa[t][3] = pack_h2(sf[2*t+1][2], sf[2*t+1][3]);
        }

        // ---- O += P V  (V row-major in smem, transposed by ldsm.trans) ----
        #pragma unroll
        for (int n = 0; n < 8; n++) {
            uint32_t vA[4], vB[4];
            const uint32_t va = base + OFF_V + (uint32_t)lane * APB + n * 16;
            ldsm4t(vA[0], vA[1], vA[2], vA[3], va);              // keys 0..31
            ldsm4t(vB[0], vB[1], vB[2], vB[3], va + 32 * APB);   // keys 32..63
            mma_fp(o[n], pa[0], &vA[0]);
            mma_fp(o[n], pa[1], &vA[2]);
            mma_fp(o[n], pa[2], &vB[0]);
            mma_fp(o[n], pa[3], &vB[2]);
        }

        cb = (cb == 3) ? 0 : cb + 1;
        lb = (lb == 3) ? 0 : lb + 1;
    }

    // ---- epilogue: o/l -> fp16 directly into final-GEMM A slot 0 ----
    const float i0 = 1.f / l0, i1 = 1.f / l1;
    const int r0 = q0 + w * 16 + (lane >> 2);
    #pragma unroll
    for (int n = 0; n < 8; n++) {
        const size_t a0 = (size_t)(b * TT + r0) * DD + h * 64 + n * 8 + c0;
        const size_t a1 = a0 + 8 * DD;
        *reinterpret_cast<uint32_t*>(&g_Af[0][a0]) = pack_h2(o[n][0] * i0, o[n][1] * i0);
        *reinterpret_cast<uint32_t*>(&g_Af[0][a1]) = pack_h2(o[n][2] * i1, o[n][3] * i1);
    }
}

// ---------------------------------------------------------------------------
// Launch
// ---------------------------------------------------------------------------
extern "C" void kernel_launch(void* const* d_in, const int* in_sizes, int n_in,
                              void* d_out, int out_size)
{
    const float* q    = (const float*)d_in[0];
    const float* k    = (const float*)d_in[1];
    const float* v    = (const float*)d_in[2];
    const int*   mask = (const int*)  d_in[3];
    const float* Wq   = (const float*)d_in[4];
    const float* bq   = (const float*)d_in[5];
    const float* Wk   = (const float*)d_in[6];
    const float* bk   = (const float*)d_in[7];
    const float* Wv   = (const float*)d_in[8];
    const float* bv   = (const float*)d_in[9];
    const float* Wo   = (const float*)d_in[10];
    const float* bo   = (const float*)d_in[11];
    float* out = (float*)d_out;

    cudaFuncSetAttribute(mma_gemm, cudaFuncAttributeMaxDynamicSharedMemorySize, GSM_TOT);
    cudaFuncSetAttribute(attn_mma, cudaFuncAttributeMaxDynamicSharedMemorySize, ASM_TOT);

    const dim3 pgrid(DD / 128, MM / 128, 3);   // batched projections
    const dim3 fgrid(DD / 128, MM / 128, 1);   // final GEMM
    const dim3 agrid(TT / 128, BB * HH);

    build_idx<<<BB, 512>>>(mask);                              // compaction FIRST
    convert_all<<<16384, 256>>>(q, k, v, Wq, Wk, Wv, Wo);      // A fp16 + W^T fp16

    mma_gemm<<<pgrid, 256, GSM_TOT>>>(bq, bk, bv, nullptr, 0); // Qh + compacted Kh/Vf

    attn_mma<<<agrid, 256, ASM_TOT>>>();                       // -> g_Af[0]

    mma_gemm<<<fgrid, 256, GSM_TOT>>>(bo, bo, bo, out, 1);     // -> out
}